// round 1
// baseline (speedup 1.0000x reference)
#include <cuda_runtime.h>
#include <math.h>

// ---------------------------------------------------------------------------
// AdaptedEntropyBottleneck:
//   y_hat = nearest-codebook quantization of x            [N,C,H,W]
//   lik   = factorized-cumulative likelihood of y_hat     [N,C,H,W]
// Since y_hat takes only K=64 values and the likelihood chain depends only on
// (channel, codebook index), lik == LUT[c][k].  We precompute the 192x64 LUT
// in a tiny kernel, then do a pure streaming pass.
// ---------------------------------------------------------------------------

#define N_  16
#define C_  192
#define H_  64
#define W_  64
#define K_  64
#define HW_ (H_ * W_)
#define EXTREMA 10.0f
#define LIK_BOUND 1e-9f

// scratch LUT: [C, K]
__device__ float d_lut[C_ * K_];

__device__ __forceinline__ float softplus_f(float v) {
    // log(1 + exp(v)); stable for large v
    return (v > 20.0f) ? v : log1pf(expf(v));
}

__device__ __forceinline__ float sigmoid_f(float v) {
    return 1.0f / (1.0f + expf(-v));
}

// Evaluate the 5-layer logits_cumulative chain for scalar v, channel c.
// mats: m0 [C,3,1], m1..m3 [C,3,3], m4 [C,1,3]
// biases: b0..b3 [C,3,1], b4 [C,1,1];  factors f0..f3 [C,3,1]
__device__ float logits_cumulative(
    float v, int c,
    const float* __restrict__ m0, const float* __restrict__ m1,
    const float* __restrict__ m2, const float* __restrict__ m3,
    const float* __restrict__ m4,
    const float* __restrict__ b0, const float* __restrict__ b1,
    const float* __restrict__ b2, const float* __restrict__ b3,
    const float* __restrict__ b4,
    const float* __restrict__ f0, const float* __restrict__ f1,
    const float* __restrict__ f2, const float* __restrict__ f3)
{
    float h[3], t[3];

    // layer 0: 1 -> 3
    #pragma unroll
    for (int o = 0; o < 3; o++) {
        float z = softplus_f(m0[c * 3 + o]) * v + b0[c * 3 + o];
        z = z + tanhf(f0[c * 3 + o]) * tanhf(z);
        h[o] = z;
    }

    const float* ms[3] = { m1, m2, m3 };
    const float* bs[3] = { b1, b2, b3 };
    const float* fs[3] = { f1, f2, f3 };

    // layers 1..3: 3 -> 3
    #pragma unroll
    for (int l = 0; l < 3; l++) {
        const float* mm = ms[l];
        const float* bb = bs[l];
        const float* ff = fs[l];
        #pragma unroll
        for (int o = 0; o < 3; o++) {
            float z = bb[c * 3 + o];
            #pragma unroll
            for (int i = 0; i < 3; i++)
                z += softplus_f(mm[c * 9 + o * 3 + i]) * h[i];
            z = z + tanhf(ff[c * 3 + o]) * tanhf(z);
            t[o] = z;
        }
        h[0] = t[0]; h[1] = t[1]; h[2] = t[2];
    }

    // layer 4: 3 -> 1
    float z = b4[c];
    #pragma unroll
    for (int i = 0; i < 3; i++)
        z += softplus_f(m4[c * 3 + i]) * h[i];
    return z;
}

// One block per channel, one thread per codebook entry.
__global__ void lut_kernel(
    const float* __restrict__ cb,
    const float* __restrict__ m0, const float* __restrict__ m1,
    const float* __restrict__ m2, const float* __restrict__ m3,
    const float* __restrict__ m4,
    const float* __restrict__ b0, const float* __restrict__ b1,
    const float* __restrict__ b2, const float* __restrict__ b3,
    const float* __restrict__ b4,
    const float* __restrict__ f0, const float* __restrict__ f1,
    const float* __restrict__ f2, const float* __restrict__ f3)
{
    int c = blockIdx.x;
    int k = threadIdx.x;
    float v = cb[k];

    float lower = logits_cumulative(v - 0.5f, c, m0, m1, m2, m3, m4,
                                    b0, b1, b2, b3, b4, f0, f1, f2, f3);
    float upper = logits_cumulative(v + 0.5f, c, m0, m1, m2, m3, m4,
                                    b0, b1, b2, b3, b4, f0, f1, f2, f3);
    float s = lower + upper;
    float sg = (s < 0.0f) ? 1.0f : ((s > 0.0f) ? -1.0f : 0.0f);
    float lik = fabsf(sigmoid_f(sg * upper) - sigmoid_f(sg * lower));
    lik = fmaxf(lik, LIK_BOUND);
    d_lut[c * K_ + k] = lik;
}

// Nearest-codebook index, replicating jnp.searchsorted(side='left') + tiebreak.
__device__ __forceinline__ int nearest_idx(float v, const float* __restrict__ s_cb) {
    int lo = 0, hi = K_;           // first index with cb[i] >= v
    #pragma unroll
    for (int s = 0; s < 6; s++) {
        int mid = (lo + hi) >> 1;
        if (s_cb[mid] < v) lo = mid + 1; else hi = mid;
    }
    int ins = lo;                  // in [0, 64]
    int i0 = (ins - 1 < 0) ? 0 : ins - 1;      // clip to [0,63]
    if (i0 > K_ - 1) i0 = K_ - 1;
    int i1 = (ins > K_ - 1) ? K_ - 1 : ins;
    float clo = s_cb[i0], chi = s_cb[i1];
    return (fabsf(chi - v) < fabsf(clo - v)) ? i1 : i0;
}

// One block per (n, c) slice: 4096 contiguous elements. 256 threads, float4 IO.
__global__ void __launch_bounds__(256)
quantize_kernel(const float* __restrict__ x,
                const float* __restrict__ cb,
                float* __restrict__ y_hat,
                float* __restrict__ lik)
{
    __shared__ float s_cb[K_];
    __shared__ float s_lut[K_];

    int c = blockIdx.x % C_;
    int t = threadIdx.x;
    if (t < K_) {
        s_cb[t]  = cb[t];
        s_lut[t] = d_lut[c * K_ + t];
    }
    __syncthreads();

    size_t base = (size_t)blockIdx.x * HW_;
    const float4* xv = reinterpret_cast<const float4*>(x + base);
    float4* yv = reinterpret_cast<float4*>(y_hat + base);
    float4* lv = reinterpret_cast<float4*>(lik + base);

    #pragma unroll
    for (int j = t; j < HW_ / 4; j += 256) {
        float4 xx = xv[j];
        int i0 = nearest_idx(xx.x, s_cb);
        int i1 = nearest_idx(xx.y, s_cb);
        int i2 = nearest_idx(xx.z, s_cb);
        int i3 = nearest_idx(xx.w, s_cb);
        float4 yy = make_float4(s_cb[i0], s_cb[i1], s_cb[i2], s_cb[i3]);
        float4 ll = make_float4(s_lut[i0], s_lut[i1], s_lut[i2], s_lut[i3]);
        yv[j] = yy;
        lv[j] = ll;
    }
}

extern "C" void kernel_launch(void* const* d_in, const int* in_sizes, int n_in,
                              void* d_out, int out_size)
{
    const float* x  = (const float*)d_in[0];
    const float* cb = (const float*)d_in[1];

    const float *m0, *m1, *m2, *m3, *m4;
    const float *b0, *b1, *b2, *b3, *b4;
    const float *f0, *f1, *f2, *f3;

    if (in_sizes[3] == C_ * 9) {
        // signature order: m0..m4, b0..b4, f0..f3
        m0 = (const float*)d_in[2];  m1 = (const float*)d_in[3];
        m2 = (const float*)d_in[4];  m3 = (const float*)d_in[5];
        m4 = (const float*)d_in[6];
        b0 = (const float*)d_in[7];  b1 = (const float*)d_in[8];
        b2 = (const float*)d_in[9];  b3 = (const float*)d_in[10];
        b4 = (const float*)d_in[11];
        f0 = (const float*)d_in[12]; f1 = (const float*)d_in[13];
        f2 = (const float*)d_in[14]; f3 = (const float*)d_in[15];
    } else {
        // dict insertion order: m0,b0,f0, m1,b1,f1, m2,b2,f2, m3,b3,f3, m4,b4
        m0 = (const float*)d_in[2];  b0 = (const float*)d_in[3];  f0 = (const float*)d_in[4];
        m1 = (const float*)d_in[5];  b1 = (const float*)d_in[6];  f1 = (const float*)d_in[7];
        m2 = (const float*)d_in[8];  b2 = (const float*)d_in[9];  f2 = (const float*)d_in[10];
        m3 = (const float*)d_in[11]; b3 = (const float*)d_in[12]; f3 = (const float*)d_in[13];
        m4 = (const float*)d_in[14]; b4 = (const float*)d_in[15];
    }

    float* out   = (float*)d_out;
    float* y_hat = out;                               // first N*C*H*W floats
    float* lik   = out + (size_t)N_ * C_ * HW_;       // second N*C*H*W floats

    lut_kernel<<<C_, K_>>>(cb, m0, m1, m2, m3, m4,
                           b0, b1, b2, b3, b4, f0, f1, f2, f3);

    quantize_kernel<<<N_ * C_, 256>>>(x, cb, y_hat, lik);
}

// round 3
// speedup vs baseline: 1.1020x; 1.1020x over previous
#include <cuda_runtime.h>
#include <math.h>

#define N_  16
#define C_  192
#define H_  64
#define W_  64
#define K_  64
#define HW_ (H_ * W_)
#define G_  4096
#define LIK_BOUND 1e-9f

// scratch: likelihood LUT [C,K] and bucket->start-index table [G]
__device__ float d_lut[C_ * K_];
__device__ __align__(16) unsigned char d_B[G_];

__device__ __forceinline__ float softplus_f(float v) {
    return (v > 20.0f) ? v : log1pf(expf(v));
}
__device__ __forceinline__ float sigmoid_f(float v) {
    return 1.0f / (1.0f + expf(-v));
}

// chain eval using pre-transformed weights in shared:
// w[0..2]   = softplus(m0)      w[3..29]  = softplus(m1,m2,m3) (9 each)
// w[30..32] = softplus(m4)      w[33..44] = tanh(f0..f3) (3 each)
// w[45..47] = b0  w[48..56] = b1,b2,b3 (3 each)  w[57] = b4
__device__ float eval_chain(float v, const float* __restrict__ w) {
    float h[3], nh[3];
    #pragma unroll
    for (int o = 0; o < 3; o++) {
        float z = w[o] * v + w[45 + o];
        z += w[33 + o] * tanhf(z);
        h[o] = z;
    }
    #pragma unroll
    for (int l = 0; l < 3; l++) {
        #pragma unroll
        for (int o = 0; o < 3; o++) {
            const float* mm = w + 3 + l * 9 + o * 3;
            float z = w[48 + l * 3 + o] + mm[0] * h[0] + mm[1] * h[1] + mm[2] * h[2];
            z += w[36 + l * 3 + o] * tanhf(z);
            nh[o] = z;
        }
        h[0] = nh[0]; h[1] = nh[1]; h[2] = nh[2];
    }
    return w[57] + w[30] * h[0] + w[31] * h[1] + w[32] * h[2];
}

// Fused prep: blocks [0,192) build the lik LUT (one channel each),
// blocks [192,256) build the bucket table (64 entries each). 64 threads.
__global__ void __launch_bounds__(64)
prep_kernel(const float* __restrict__ cb,
            const float* __restrict__ m0, const float* __restrict__ m1,
            const float* __restrict__ m2, const float* __restrict__ m3,
            const float* __restrict__ m4,
            const float* __restrict__ b0, const float* __restrict__ b1,
            const float* __restrict__ b2, const float* __restrict__ b3,
            const float* __restrict__ b4,
            const float* __restrict__ f0, const float* __restrict__ f1,
            const float* __restrict__ f2, const float* __restrict__ f3)
{
    int t = threadIdx.x;

    if (blockIdx.x < C_) {
        // ---- LUT part ----
        __shared__ float w[58];
        int c = blockIdx.x;
        if (t < 33) {
            float raw;
            if (t < 3)       raw = m0[c * 3 + t];
            else if (t < 12) raw = m1[c * 9 + (t - 3)];
            else if (t < 21) raw = m2[c * 9 + (t - 12)];
            else if (t < 30) raw = m3[c * 9 + (t - 21)];
            else             raw = m4[c * 3 + (t - 30)];
            w[t] = softplus_f(raw);
        } else if (t < 45) {
            int i = t - 33;
            const float* fp = (i < 3) ? f0 : (i < 6) ? f1 : (i < 9) ? f2 : f3;
            w[t] = tanhf(fp[c * 3 + (i % 3)]);
        } else if (t < 58) {
            int i = t - 45;
            float raw;
            if (i < 3)       raw = b0[c * 3 + i];
            else if (i < 6)  raw = b1[c * 3 + (i - 3)];
            else if (i < 9)  raw = b2[c * 3 + (i - 6)];
            else if (i < 12) raw = b3[c * 3 + (i - 9)];
            else             raw = b4[c];
            w[t] = raw;
        }
        __syncthreads();

        float v = cb[t];
        float lower = eval_chain(v - 0.5f, w);
        float upper = eval_chain(v + 0.5f, w);
        float s  = lower + upper;
        float sg = (s < 0.0f) ? 1.0f : ((s > 0.0f) ? -1.0f : 0.0f);
        float lik = fabsf(sigmoid_f(sg * upper) - sigmoid_f(sg * lower));
        d_lut[c * K_ + t] = fmaxf(lik, LIK_BOUND);
    } else {
        // ---- bucket table part ----
        __shared__ float s_cb[K_];
        s_cb[t] = cb[t];
        __syncthreads();
        int g = (blockIdx.x - C_) * 64 + t;
        // conservative lower edge of bucket g (guard > bucket-map rounding error)
        float e = -16.0f + (float)g * 0.0078125f - 2e-5f;
        int cnt = 0;
        #pragma unroll
        for (int j = 0; j < K_ - 1; j++)
            cnt += (fabsf(s_cb[j + 1] - e) < fabsf(s_cb[j] - e)) ? 1 : 0;
        d_B[g] = (unsigned char)cnt;
    }
}

__device__ __forceinline__ void lookup(float v,
                                       const float* __restrict__ s_cb,
                                       const unsigned char* __restrict__ s_B,
                                       const float2* __restrict__ s_yl,
                                       float& y, float& l)
{
    int g = __float2int_rd((v + 16.0f) * 128.0f);
    g = max(0, min(g, G_ - 1));
    int j = s_B[g];
    // exact reference predicate; monotone in j -> converges to searchsorted+tiebreak index
    while (fabsf(s_cb[j + 1] - v) < fabsf(s_cb[j] - v)) j++;
    float2 r = s_yl[j];
    y = r.x; l = r.y;
}

// Each block: one channel c, four n-slices (4 * 4096 elements). 256 threads.
__global__ void __launch_bounds__(256)
quantize_kernel(const float* __restrict__ x,
                const float* __restrict__ cb,
                float* __restrict__ y_hat,
                float* __restrict__ lik)
{
    __shared__ float s_cb[K_ + 2];          // [64] = +inf sentinel
    __shared__ float2 s_yl[K_];
    __shared__ __align__(16) unsigned char s_B[G_];

    int t = threadIdx.x;
    int c  = blockIdx.x % C_;
    int nq = blockIdx.x / C_;

    if (t < K_) {
        float cv = cb[t];
        s_cb[t] = cv;
        s_yl[t] = make_float2(cv, d_lut[c * K_ + t]);
    }
    if (t == 64) s_cb[K_] = __int_as_float(0x7f800000);  // +inf
    ((int4*)s_B)[t] = ((const int4*)d_B)[t];             // 256 * 16B = 4096B
    __syncthreads();

    #pragma unroll
    for (int s = 0; s < 4; s++) {
        int n = nq * 4 + s;
        size_t base = ((size_t)n * C_ + c) * HW_;
        const float4* xv = reinterpret_cast<const float4*>(x + base);
        float4* yv = reinterpret_cast<float4*>(y_hat + base);
        float4* lv = reinterpret_cast<float4*>(lik + base);

        #pragma unroll
        for (int it = 0; it < HW_ / 4 / 256; it++) {
            int j = t + it * 256;
            float4 xx = xv[j];
            float4 yy, ll;
            lookup(xx.x, s_cb, s_B, s_yl, yy.x, ll.x);
            lookup(xx.y, s_cb, s_B, s_yl, yy.y, ll.y);
            lookup(xx.z, s_cb, s_B, s_yl, yy.z, ll.z);
            lookup(xx.w, s_cb, s_B, s_yl, yy.w, ll.w);
            yv[j] = yy;
            lv[j] = ll;
        }
    }
}

extern "C" void kernel_launch(void* const* d_in, const int* in_sizes, int n_in,
                              void* d_out, int out_size)
{
    const float* x  = (const float*)d_in[0];
    const float* cb = (const float*)d_in[1];

    const float *m0, *m1, *m2, *m3, *m4;
    const float *b0, *b1, *b2, *b3, *b4;
    const float *f0, *f1, *f2, *f3;

    if (in_sizes[3] == C_ * 9) {
        // signature order: m0..m4, b0..b4, f0..f3
        m0 = (const float*)d_in[2];  m1 = (const float*)d_in[3];
        m2 = (const float*)d_in[4];  m3 = (const float*)d_in[5];
        m4 = (const float*)d_in[6];
        b0 = (const float*)d_in[7];  b1 = (const float*)d_in[8];
        b2 = (const float*)d_in[9];  b3 = (const float*)d_in[10];
        b4 = (const float*)d_in[11];
        f0 = (const float*)d_in[12]; f1 = (const float*)d_in[13];
        f2 = (const float*)d_in[14]; f3 = (const float*)d_in[15];
    } else {
        // dict insertion order: m0,b0,f0, m1,b1,f1, ...
        m0 = (const float*)d_in[2];  b0 = (const float*)d_in[3];  f0 = (const float*)d_in[4];
        m1 = (const float*)d_in[5];  b1 = (const float*)d_in[6];  f1 = (const float*)d_in[7];
        m2 = (const float*)d_in[8];  b2 = (const float*)d_in[9];  f2 = (const float*)d_in[10];
        m3 = (const float*)d_in[11]; b3 = (const float*)d_in[12]; f3 = (const float*)d_in[13];
        m4 = (const float*)d_in[14]; b4 = (const float*)d_in[15];
    }

    float* out   = (float*)d_out;
    float* y_hat = out;
    float* lik   = out + (size_t)N_ * C_ * HW_;

    prep_kernel<<<C_ + G_ / 64, 64>>>(cb, m0, m1, m2, m3, m4,
                                      b0, b1, b2, b3, b4, f0, f1, f2, f3);

    quantize_kernel<<<(N_ / 4) * C_, 256>>>(x, cb, y_hat, lik);
}

// round 4
// speedup vs baseline: 1.1739x; 1.0652x over previous
#include <cuda_runtime.h>
#include <math.h>

#define N_  16
#define C_  192
#define H_  64
#define W_  64
#define K_  64
#define HW_ (H_ * W_)
#define G_  4096
#define LIK_BOUND 1e-9f

// scratch: likelihood LUT [C,K] and bucket->start-index table [G]
__device__ float d_lut[C_ * K_];
__device__ __align__(16) unsigned char d_B[G_];

__device__ __forceinline__ float softplus_f(float v) {
    return (v > 20.0f) ? v : log1pf(expf(v));
}
__device__ __forceinline__ float sigmoid_f(float v) {
    return 1.0f / (1.0f + expf(-v));
}

// chain eval using pre-transformed weights in shared:
// w[0..2]   = softplus(m0)      w[3..29]  = softplus(m1,m2,m3) (9 each)
// w[30..32] = softplus(m4)      w[33..44] = tanh(f0..f3) (3 each)
// w[45..47] = b0  w[48..56] = b1,b2,b3 (3 each)  w[57] = b4
__device__ float eval_chain(float v, const float* __restrict__ w) {
    float h[3], nh[3];
    #pragma unroll
    for (int o = 0; o < 3; o++) {
        float z = w[o] * v + w[45 + o];
        z += w[33 + o] * tanhf(z);
        h[o] = z;
    }
    #pragma unroll
    for (int l = 0; l < 3; l++) {
        #pragma unroll
        for (int o = 0; o < 3; o++) {
            const float* mm = w + 3 + l * 9 + o * 3;
            float z = w[48 + l * 3 + o] + mm[0] * h[0] + mm[1] * h[1] + mm[2] * h[2];
            z += w[36 + l * 3 + o] * tanhf(z);
            nh[o] = z;
        }
        h[0] = nh[0]; h[1] = nh[1]; h[2] = nh[2];
    }
    return w[57] + w[30] * h[0] + w[31] * h[1] + w[32] * h[2];
}

// Fused prep, 128 threads/block:
//   blocks [0,192): lik LUT for one channel; t<64 -> lower(k=t), t>=64 -> upper(k=t-64)
//   blocks [192,224): bucket table, 128 entries each
__global__ void __launch_bounds__(128)
prep_kernel(const float* __restrict__ cb,
            const float* __restrict__ m0, const float* __restrict__ m1,
            const float* __restrict__ m2, const float* __restrict__ m3,
            const float* __restrict__ m4,
            const float* __restrict__ b0, const float* __restrict__ b1,
            const float* __restrict__ b2, const float* __restrict__ b3,
            const float* __restrict__ b4,
            const float* __restrict__ f0, const float* __restrict__ f1,
            const float* __restrict__ f2, const float* __restrict__ f3)
{
    int t = threadIdx.x;

    if (blockIdx.x < C_) {
        // ---- LUT part ----
        __shared__ float w[58];
        __shared__ float ev[2][K_];
        int c = blockIdx.x;
        if (t < 33) {
            float raw;
            if (t < 3)       raw = m0[c * 3 + t];
            else if (t < 12) raw = m1[c * 9 + (t - 3)];
            else if (t < 21) raw = m2[c * 9 + (t - 12)];
            else if (t < 30) raw = m3[c * 9 + (t - 21)];
            else             raw = m4[c * 3 + (t - 30)];
            w[t] = softplus_f(raw);
        } else if (t < 45) {
            int i = t - 33;
            const float* fp = (i < 3) ? f0 : (i < 6) ? f1 : (i < 9) ? f2 : f3;
            w[t] = tanhf(fp[c * 3 + (i % 3)]);
        } else if (t < 58) {
            int i = t - 45;
            float raw;
            if (i < 3)       raw = b0[c * 3 + i];
            else if (i < 6)  raw = b1[c * 3 + (i - 3)];
            else if (i < 9)  raw = b2[c * 3 + (i - 6)];
            else if (i < 12) raw = b3[c * 3 + (i - 9)];
            else             raw = b4[c];
            w[t] = raw;
        }
        __syncthreads();

        int k = t & 63;
        float off = (t < 64) ? -0.5f : 0.5f;
        ev[t >> 6][k] = eval_chain(cb[k] + off, w);
        __syncthreads();

        if (t < K_) {
            float lower = ev[0][t], upper = ev[1][t];
            float s  = lower + upper;
            float sg = (s < 0.0f) ? 1.0f : ((s > 0.0f) ? -1.0f : 0.0f);
            float lik = fabsf(sigmoid_f(sg * upper) - sigmoid_f(sg * lower));
            d_lut[c * K_ + t] = fmaxf(lik, LIK_BOUND);
        }
    } else {
        // ---- bucket table part ----
        __shared__ float s_cb[K_];
        if (t < K_) s_cb[t] = cb[t];
        __syncthreads();
        int g = (blockIdx.x - C_) * 128 + t;
        // conservative lower edge of bucket g (guard > bucket-map rounding error)
        float e = -16.0f + (float)g * 0.0078125f - 2e-5f;
        int cnt = 0;
        #pragma unroll
        for (int j = 0; j < K_ - 1; j++)
            cnt += (fabsf(s_cb[j + 1] - e) < fabsf(s_cb[j] - e)) ? 1 : 0;
        d_B[g] = (unsigned char)cnt;
    }
}

__device__ __forceinline__ void lookup(float v,
                                       const float2* __restrict__ s_pair,
                                       const unsigned char* __restrict__ s_B,
                                       const float2* __restrict__ s_yl,
                                       float& y, float& l)
{
    int g = __float2int_rd((v + 16.0f) * 128.0f);
    g = max(0, min(g, G_ - 1));
    int j = s_B[g];
    // exact reference predicate; monotone in j -> converges to searchsorted+tiebreak
    float2 p = s_pair[j];
    while (fabsf(p.y - v) < fabsf(p.x - v)) { j++; p = s_pair[j]; }
    float2 r = s_yl[j];
    y = r.x; l = r.y;
}

// One block per (n,c) slice: 4096 contiguous elements. 256 threads, float4 IO.
__global__ void __launch_bounds__(256)
quantize_kernel(const float* __restrict__ x,
                const float* __restrict__ cb,
                float* __restrict__ y_hat,
                float* __restrict__ lik)
{
    __shared__ float2 s_pair[K_];   // (cb[j], cb[j+1]); last has +inf sentinel
    __shared__ float2 s_yl[K_];     // (cb[j], lut[c][j])
    __shared__ __align__(16) unsigned char s_B[G_];

    int t = threadIdx.x;
    int c = blockIdx.x % C_;

    if (t < K_) {
        float cv  = cb[t];
        float cvn = (t < K_ - 1) ? cb[t + 1] : __int_as_float(0x7f800000);
        s_pair[t] = make_float2(cv, cvn);
        s_yl[t]   = make_float2(cv, d_lut[c * K_ + t]);
    }
    ((int4*)s_B)[t] = ((const int4*)d_B)[t];   // 256 * 16B = 4096B
    __syncthreads();

    size_t base = (size_t)blockIdx.x * HW_;
    const float4* xv = reinterpret_cast<const float4*>(x + base);
    float4* yv = reinterpret_cast<float4*>(y_hat + base);
    float4* lv = reinterpret_cast<float4*>(lik + base);

    #pragma unroll
    for (int it = 0; it < HW_ / 4 / 256; it++) {
        int j = t + it * 256;
        float4 xx = xv[j];
        float4 yy, ll;
        lookup(xx.x, s_pair, s_B, s_yl, yy.x, ll.x);
        lookup(xx.y, s_pair, s_B, s_yl, yy.y, ll.y);
        lookup(xx.z, s_pair, s_B, s_yl, yy.z, ll.z);
        lookup(xx.w, s_pair, s_B, s_yl, yy.w, ll.w);
        yv[j] = yy;
        lv[j] = ll;
    }
}

extern "C" void kernel_launch(void* const* d_in, const int* in_sizes, int n_in,
                              void* d_out, int out_size)
{
    const float* x  = (const float*)d_in[0];
    const float* cb = (const float*)d_in[1];

    const float *m0, *m1, *m2, *m3, *m4;
    const float *b0, *b1, *b2, *b3, *b4;
    const float *f0, *f1, *f2, *f3;

    if (in_sizes[3] == C_ * 9) {
        // signature order: m0..m4, b0..b4, f0..f3
        m0 = (const float*)d_in[2];  m1 = (const float*)d_in[3];
        m2 = (const float*)d_in[4];  m3 = (const float*)d_in[5];
        m4 = (const float*)d_in[6];
        b0 = (const float*)d_in[7];  b1 = (const float*)d_in[8];
        b2 = (const float*)d_in[9];  b3 = (const float*)d_in[10];
        b4 = (const float*)d_in[11];
        f0 = (const float*)d_in[12]; f1 = (const float*)d_in[13];
        f2 = (const float*)d_in[14]; f3 = (const float*)d_in[15];
    } else {
        // dict insertion order: m0,b0,f0, m1,b1,f1, ...
        m0 = (const float*)d_in[2];  b0 = (const float*)d_in[3];  f0 = (const float*)d_in[4];
        m1 = (const float*)d_in[5];  b1 = (const float*)d_in[6];  f1 = (const float*)d_in[7];
        m2 = (const float*)d_in[8];  b2 = (const float*)d_in[9];  f2 = (const float*)d_in[10];
        m3 = (const float*)d_in[11]; b3 = (const float*)d_in[12]; f3 = (const float*)d_in[13];
        m4 = (const float*)d_in[14]; b4 = (const float*)d_in[15];
    }

    float* out   = (float*)d_out;
    float* y_hat = out;
    float* lik   = out + (size_t)N_ * C_ * HW_;

    prep_kernel<<<C_ + G_ / 128, 128>>>(cb, m0, m1, m2, m3, m4,
                                        b0, b1, b2, b3, b4, f0, f1, f2, f3);

    quantize_kernel<<<N_ * C_, 256>>>(x, cb, y_hat, lik);
}

// round 5
// speedup vs baseline: 1.2474x; 1.0626x over previous
#include <cuda_runtime.h>
#include <math.h>

#define N_  16
#define C_  192
#define H_  64
#define W_  64
#define K_  64
#define HW_ (H_ * W_)
#define G_  4096
#define LIK_BOUND 1e-9f

// scratch: likelihood LUT [C,K] and bucket table [G] (idx | 0x80 if impure)
__device__ float d_lut[C_ * K_];
__device__ __align__(16) unsigned char d_B[G_];

__device__ __forceinline__ float softplus_f(float v) {
    return (v > 20.0f) ? v : log1pf(expf(v));
}
__device__ __forceinline__ float sigmoid_f(float v) {
    return 1.0f / (1.0f + expf(-v));
}

// chain eval using pre-transformed weights in shared:
// w[0..2]   = softplus(m0)      w[3..29]  = softplus(m1,m2,m3) (9 each)
// w[30..32] = softplus(m4)      w[33..44] = tanh(f0..f3) (3 each)
// w[45..47] = b0  w[48..56] = b1,b2,b3 (3 each)  w[57] = b4
__device__ float eval_chain(float v, const float* __restrict__ w) {
    float h[3], nh[3];
    #pragma unroll
    for (int o = 0; o < 3; o++) {
        float z = w[o] * v + w[45 + o];
        z += w[33 + o] * tanhf(z);
        h[o] = z;
    }
    #pragma unroll
    for (int l = 0; l < 3; l++) {
        #pragma unroll
        for (int o = 0; o < 3; o++) {
            const float* mm = w + 3 + l * 9 + o * 3;
            float z = w[48 + l * 3 + o] + mm[0] * h[0] + mm[1] * h[1] + mm[2] * h[2];
            z += w[36 + l * 3 + o] * tanhf(z);
            nh[o] = z;
        }
        h[0] = nh[0]; h[1] = nh[1]; h[2] = nh[2];
    }
    return w[57] + w[30] * h[0] + w[31] * h[1] + w[32] * h[2];
}

// count-form nearest index at probe e (exact reference semantics)
__device__ __forceinline__ int nearest_cnt(float e, const float* __restrict__ s_cb) {
    int cnt = 0;
    #pragma unroll
    for (int j = 0; j < K_ - 1; j++)
        cnt += (fabsf(s_cb[j + 1] - e) < fabsf(s_cb[j] - e)) ? 1 : 0;
    return cnt;
}

// Fused prep, 128 threads/block:
//   blocks [0,192): lik LUT for one channel; t<64 -> lower(k=t), t>=64 -> upper
//   blocks [192,224): bucket table with purity flag, 128 entries each
__global__ void __launch_bounds__(128)
prep_kernel(const float* __restrict__ cb,
            const float* __restrict__ m0, const float* __restrict__ m1,
            const float* __restrict__ m2, const float* __restrict__ m3,
            const float* __restrict__ m4,
            const float* __restrict__ b0, const float* __restrict__ b1,
            const float* __restrict__ b2, const float* __restrict__ b3,
            const float* __restrict__ b4,
            const float* __restrict__ f0, const float* __restrict__ f1,
            const float* __restrict__ f2, const float* __restrict__ f3)
{
    int t = threadIdx.x;

    if (blockIdx.x < C_) {
        // ---- LUT part ----
        __shared__ float w[58];
        __shared__ float ev[2][K_];
        int c = blockIdx.x;
        if (t < 33) {
            float raw;
            if (t < 3)       raw = m0[c * 3 + t];
            else if (t < 12) raw = m1[c * 9 + (t - 3)];
            else if (t < 21) raw = m2[c * 9 + (t - 12)];
            else if (t < 30) raw = m3[c * 9 + (t - 21)];
            else             raw = m4[c * 3 + (t - 30)];
            w[t] = softplus_f(raw);
        } else if (t < 45) {
            int i = t - 33;
            const float* fp = (i < 3) ? f0 : (i < 6) ? f1 : (i < 9) ? f2 : f3;
            w[t] = tanhf(fp[c * 3 + (i % 3)]);
        } else if (t < 58) {
            int i = t - 45;
            float raw;
            if (i < 3)       raw = b0[c * 3 + i];
            else if (i < 6)  raw = b1[c * 3 + (i - 3)];
            else if (i < 9)  raw = b2[c * 3 + (i - 6)];
            else if (i < 12) raw = b3[c * 3 + (i - 9)];
            else             raw = b4[c];
            w[t] = raw;
        }
        __syncthreads();

        int k = t & 63;
        float off = (t < 64) ? -0.5f : 0.5f;
        ev[t >> 6][k] = eval_chain(cb[k] + off, w);
        __syncthreads();

        if (t < K_) {
            float lower = ev[0][t], upper = ev[1][t];
            float s  = lower + upper;
            float sg = (s < 0.0f) ? 1.0f : ((s > 0.0f) ? -1.0f : 0.0f);
            float lik = fabsf(sigmoid_f(sg * upper) - sigmoid_f(sg * lower));
            d_lut[c * K_ + t] = fmaxf(lik, LIK_BOUND);
        }
    } else {
        // ---- bucket table with purity flag ----
        __shared__ float s_cb[K_];
        if (t < K_) s_cb[t] = cb[t];
        __syncthreads();
        int g = (blockIdx.x - C_) * 128 + t;
        // guards (2e-5) dominate bucket-map float rounding (~4e-6)
        float e_lo = -16.0f + (float)g       * 0.0078125f - 2e-5f;
        float e_hi = -16.0f + (float)(g + 1) * 0.0078125f + 2e-5f;
        int c_lo = nearest_cnt(e_lo, s_cb);
        int c_hi = nearest_cnt(e_hi, s_cb);
        d_B[g] = (unsigned char)(c_lo | ((c_lo == c_hi) ? 0 : 0x80));
    }
}

__device__ __forceinline__ void lookup(float v,
                                       const float2* __restrict__ s_pair,
                                       const unsigned char* __restrict__ s_B,
                                       const float2* __restrict__ s_yl,
                                       float& y, float& l)
{
    int g = __float2int_rd((v + 16.0f) * 128.0f);
    g = max(0, min(g, G_ - 1));
    int b = s_B[g];
    int j = b & 0x7f;
    if (b & 0x80) {
        // boundary bucket: resolve with exact reference predicate (monotone walk)
        float2 p = s_pair[j];
        while (fabsf(p.y - v) < fabsf(p.x - v)) { j++; p = s_pair[j]; }
    }
    float2 r = s_yl[j];
    y = r.x; l = r.y;
}

// One block per (n,c) slice: 4096 contiguous elements. 256 threads, float4 IO.
__global__ void __launch_bounds__(256)
quantize_kernel(const float* __restrict__ x,
                const float* __restrict__ cb,
                float* __restrict__ y_hat,
                float* __restrict__ lik)
{
    __shared__ float2 s_pair[K_];   // (cb[j], cb[j+1]); last has +inf sentinel
    __shared__ float2 s_yl[K_];     // (cb[j], lut[c][j])
    __shared__ __align__(16) unsigned char s_B[G_];

    int t = threadIdx.x;
    int c = blockIdx.x % C_;

    if (t < K_) {
        float cv  = cb[t];
        float cvn = (t < K_ - 1) ? cb[t + 1] : __int_as_float(0x7f800000);
        s_pair[t] = make_float2(cv, cvn);
        s_yl[t]   = make_float2(cv, d_lut[c * K_ + t]);
    }
    ((int4*)s_B)[t] = ((const int4*)d_B)[t];   // 256 * 16B = 4096B
    __syncthreads();

    size_t base = (size_t)blockIdx.x * HW_;
    const float4* xv = reinterpret_cast<const float4*>(x + base);
    float4* yv = reinterpret_cast<float4*>(y_hat + base);
    float4* lv = reinterpret_cast<float4*>(lik + base);

    #pragma unroll
    for (int it = 0; it < HW_ / 4 / 256; it++) {
        int j = t + it * 256;
        float4 xx = xv[j];
        float4 yy, ll;
        lookup(xx.x, s_pair, s_B, s_yl, yy.x, ll.x);
        lookup(xx.y, s_pair, s_B, s_yl, yy.y, ll.y);
        lookup(xx.z, s_pair, s_B, s_yl, yy.z, ll.z);
        lookup(xx.w, s_pair, s_B, s_yl, yy.w, ll.w);
        yv[j] = yy;
        lv[j] = ll;
    }
}

extern "C" void kernel_launch(void* const* d_in, const int* in_sizes, int n_in,
                              void* d_out, int out_size)
{
    const float* x  = (const float*)d_in[0];
    const float* cb = (const float*)d_in[1];

    const float *m0, *m1, *m2, *m3, *m4;
    const float *b0, *b1, *b2, *b3, *b4;
    const float *f0, *f1, *f2, *f3;

    if (in_sizes[3] == C_ * 9) {
        // signature order: m0..m4, b0..b4, f0..f3
        m0 = (const float*)d_in[2];  m1 = (const float*)d_in[3];
        m2 = (const float*)d_in[4];  m3 = (const float*)d_in[5];
        m4 = (const float*)d_in[6];
        b0 = (const float*)d_in[7];  b1 = (const float*)d_in[8];
        b2 = (const float*)d_in[9];  b3 = (const float*)d_in[10];
        b4 = (const float*)d_in[11];
        f0 = (const float*)d_in[12]; f1 = (const float*)d_in[13];
        f2 = (const float*)d_in[14]; f3 = (const float*)d_in[15];
    } else {
        // dict insertion order: m0,b0,f0, m1,b1,f1, ...
        m0 = (const float*)d_in[2];  b0 = (const float*)d_in[3];  f0 = (const float*)d_in[4];
        m1 = (const float*)d_in[5];  b1 = (const float*)d_in[6];  f1 = (const float*)d_in[7];
        m2 = (const float*)d_in[8];  b2 = (const float*)d_in[9];  f2 = (const float*)d_in[10];
        m3 = (const float*)d_in[11]; b3 = (const float*)d_in[12]; f3 = (const float*)d_in[13];
        m4 = (const float*)d_in[14]; b4 = (const float*)d_in[15];
    }

    float* out   = (float*)d_out;
    float* y_hat = out;
    float* lik   = out + (size_t)N_ * C_ * HW_;

    prep_kernel<<<C_ + G_ / 128, 128>>>(cb, m0, m1, m2, m3, m4,
                                        b0, b1, b2, b3, b4, f0, f1, f2, f3);

    quantize_kernel<<<N_ * C_, 256>>>(x, cb, y_hat, lik);
}